// round 2
// baseline (speedup 1.0000x reference)
#include <cuda_runtime.h>
#include <math.h>

#define B_    128
#define H_    64
#define W_    126
#define HW_   8064          // H_*W_
#define BC_   8192          // B_*64
#define NMODE 4096          // 64*64

// ---------------- device scratch ----------------
__device__ __align__(16) float g_x  [BC_ * (size_t)HW_];   // spatial [bc][h][w]
__device__ __align__(16) float g_s1 [BC_ * (size_t)8192];  // staging A
__device__ __align__(16) float g_xf [BC_ * (size_t)8192];  // staging B
__device__ __align__(16) float g_xfm[NMODE * (size_t)16384]; // mode-major [mode][b*2+ri][i]
__device__ __align__(16) float g_wt [NMODE * (size_t)4096];  // [mode][i][o]
__device__ __align__(16) float g_fwdW[126 * 128];  // [w][n]  fwd width basis
__device__ __align__(16) float g_invW[128 * 128];  // [n][w]  inv width basis (padded)
__device__ __align__(16) float g_Gt  [128 * 128];  // [j][m]  fwd height basis^T
__device__ __align__(16) float g_G2t [128 * 128];  // [j][m]  inv height basis^T
__device__ __align__(16) float g_mw  [4096];       // effective sigmoid mask

// ---------------- basis precompute ----------------
__global__ void k_basis(const float* __restrict__ mwin) {
    int i = blockIdx.x * blockDim.x + threadIdx.x;
    const double PI2 = 6.283185307179586476925286766559;
    if (i < 126 * 128) {
        int w = i / 128, n = i % 128, k = n & 63;
        double th = PI2 * (double)(k * w) / 126.0;
        g_fwdW[i] = (n < 64) ? (float)cos(th) : (float)(-sin(th));
    }
    if (i < 128 * 128) {
        int j = i / 128, w = i % 128;
        float v = 0.f;
        if (w < 126) {
            int k = j & 63;
            double a = (k == 0 || k == 63) ? (1.0 / 126.0) : (2.0 / 126.0);
            double th = PI2 * (double)(k * w) / 126.0;
            v = (j < 64) ? (float)(a * cos(th)) : (float)(-a * sin(th));
        }
        g_invW[i] = v;
    }
    if (i < 128 * 128) {
        int j = i / 128, m = i % 128;
        int ky = m & 63, h = j & 63;
        double th = PI2 * (double)(ky * h) / 64.0;
        double c = cos(th), s = sin(th);
        g_Gt[i] = (float)((m < 64) ? ((j < 64) ? c : s) : ((j < 64) ? -s : c));
    }
    if (i < 128 * 128) {
        int j = i / 128, m = i % 128;
        int h = m & 63, ky = j & 63;
        double th = PI2 * (double)(ky * h) / 64.0;
        double c = cos(th) / 64.0, s = sin(th) / 64.0;
        g_G2t[i] = (float)((m < 64) ? ((j < 64) ? c : -s) : ((j < 64) ? s : c));
    }
    if (i < 4096) {
        int ky = i >> 6, kx = i & 63;
        float s1 = 1.f / (1.f + expf(-mwin[i]));
        if (kx == 0 || kx == 63) {
            float s2 = 1.f / (1.f + expf(-mwin[(((64 - ky) & 63) << 6) + kx]));
            s1 = 0.5f * (s1 + s2);
        }
        g_mw[i] = s1;
    }
}

// ---------------- encoder 1x1 conv 3 -> 64 ----------------
__global__ __launch_bounds__(256) void k_enc(const float* __restrict__ xin,
                                             const float* __restrict__ ew,
                                             const float* __restrict__ eb) {
    __shared__ float sx[3 * 126];
    __shared__ float sw[192];
    __shared__ float sb[64];
    int b = blockIdx.x >> 6, h = blockIdx.x & 63;
    int t = threadIdx.x;
    if (t < 192) sw[t] = ew[t];
    if (t < 64)  sb[t] = eb[t];
    for (int idx = t; idx < 378; idx += 256) {
        int j = idx / 126, w = idx % 126;
        sx[idx] = xin[(size_t)(b * 3 + j) * HW_ + h * 126 + w];
    }
    __syncthreads();
    for (int idx = t; idx < 64 * 126; idx += 256) {
        int c = idx / 126, w = idx % 126;
        float v = sb[c] + sw[c * 3] * sx[w] + sw[c * 3 + 1] * sx[126 + w]
                        + sw[c * 3 + 2] * sx[252 + w];
        g_x[(size_t)(b * 64 + c) * HW_ + h * 126 + w] = v;
    }
}

// ---------------- forward width DFT: x[64][126] -> s1[ri][h][kx] ----------------
__global__ __launch_bounds__(256) void k_fwdW() {
    extern __shared__ float sm[];
    float* As = sm;               // [64][129]
    float* Bs = sm + 64 * 129;    // [126][128]
    int bc = blockIdx.x, t = threadIdx.x;
    const float* src = g_x + (size_t)bc * HW_;
    for (int idx = t; idx < HW_; idx += 256) {
        int h = idx / 126, w = idx % 126;
        As[h * 129 + w] = src[idx];
    }
    for (int idx = t; idx < 126 * 128; idx += 256) Bs[idx] = g_fwdW[idx];
    __syncthreads();
    int ty = t >> 4, tx = t & 15;
    float acc[4][8];
#pragma unroll
    for (int r = 0; r < 4; r++)
#pragma unroll
        for (int c = 0; c < 8; c++) acc[r][c] = 0.f;
#pragma unroll 2
    for (int k = 0; k < 126; k++) {
        float a[4];
#pragma unroll
        for (int r = 0; r < 4; r++) a[r] = As[(ty * 4 + r) * 129 + k];
        float4 b0 = *(const float4*)(Bs + k * 128 + tx * 8);
        float4 b1 = *(const float4*)(Bs + k * 128 + tx * 8 + 4);
        float bb[8] = {b0.x, b0.y, b0.z, b0.w, b1.x, b1.y, b1.z, b1.w};
#pragma unroll
        for (int r = 0; r < 4; r++)
#pragma unroll
            for (int c = 0; c < 8; c++) acc[r][c] = fmaf(a[r], bb[c], acc[r][c]);
    }
    float* out = g_s1 + (size_t)bc * 8192;
    int n0 = tx * 8, ri = n0 >> 6, kx0 = n0 & 63;
#pragma unroll
    for (int r = 0; r < 4; r++) {
        int h = ty * 4 + r;
        *(float4*)(out + ri * 4096 + h * 64 + kx0) =
            make_float4(acc[r][0], acc[r][1], acc[r][2], acc[r][3]);
        *(float4*)(out + ri * 4096 + h * 64 + kx0 + 4) =
            make_float4(acc[r][4], acc[r][5], acc[r][6], acc[r][7]);
    }
}

// ---------------- height transform (fwd applies mweff) ----------------
__global__ __launch_bounds__(256) void k_hdft(int fwd) {
    extern __shared__ float sm[];
    float* Gs = sm;           // [j][m] 128x128
    float* Ss = sm + 16384;   // [j][kx] 128x64
    int bc = blockIdx.x, t = threadIdx.x;
    const float* basisT = fwd ? g_Gt : g_G2t;
    const float* in  = fwd ? g_s1 : g_xf;
    float*       out = fwd ? g_xf : g_s1;
    for (int idx = t; idx < 16384; idx += 256) Gs[idx] = basisT[idx];
    const float* src = in + (size_t)bc * 8192;
    for (int idx = t; idx < 8192; idx += 256) Ss[idx] = src[idx];
    __syncthreads();
    int ty = t >> 4, tx = t & 15;   // m-group 8, kx-group 4
    float acc[8][4];
#pragma unroll
    for (int r = 0; r < 8; r++)
#pragma unroll
        for (int c = 0; c < 4; c++) acc[r][c] = 0.f;
#pragma unroll 2
    for (int j = 0; j < 128; j++) {
        float4 a0 = *(const float4*)(Gs + j * 128 + ty * 8);
        float4 a1 = *(const float4*)(Gs + j * 128 + ty * 8 + 4);
        float4 b  = *(const float4*)(Ss + j * 64 + tx * 4);
        float aa[8] = {a0.x, a0.y, a0.z, a0.w, a1.x, a1.y, a1.z, a1.w};
        float bv[4] = {b.x, b.y, b.z, b.w};
#pragma unroll
        for (int r = 0; r < 8; r++)
#pragma unroll
            for (int c = 0; c < 4; c++) acc[r][c] = fmaf(aa[r], bv[c], acc[r][c]);
    }
    float* dst = out + (size_t)bc * 8192;
#pragma unroll
    for (int r = 0; r < 8; r++) {
        int m = ty * 8 + r;
        float4 v = make_float4(acc[r][0], acc[r][1], acc[r][2], acc[r][3]);
        if (fwd) {
            float4 w = *(const float4*)(g_mw + (m & 63) * 64 + tx * 4);
            v.x *= w.x; v.y *= w.y; v.z *= w.z; v.w *= w.w;
        }
        *(float4*)(dst + m * 64 + tx * 4) = v;
    }
}

// ---------------- transpose to mode-major ----------------
__global__ __launch_bounds__(256) void k_t1() {
    __shared__ float s[128 * 65];
    int b = blockIdx.x >> 6, ky = blockIdx.x & 63;
    int t = threadIdx.x;
    for (int idx = t; idx < 8192; idx += 256) {
        int i = idx >> 7, r = idx & 127, ri = r >> 6, kx = r & 63;
        s[(ri * 64 + i) * 65 + kx] =
            g_xf[(size_t)(b * 64 + i) * 8192 + ri * 4096 + ky * 64 + kx];
    }
    __syncthreads();
    for (int idx = t; idx < 8192; idx += 256) {
        int kx = idx >> 7, c = idx & 127;
        g_xfm[(size_t)(ky * 64 + kx) * 16384 + b * 128 + c] = s[c * 65 + kx];
    }
}

// ---------------- transpose back from mode-major ----------------
__global__ __launch_bounds__(256) void k_t2() {
    __shared__ float s[128 * 65];
    int b = blockIdx.x >> 6, ky = blockIdx.x & 63;
    int t = threadIdx.x;
    for (int idx = t; idx < 8192; idx += 256) {
        int kx = idx >> 7, c = idx & 127;
        s[c * 65 + kx] = g_s1[(size_t)(ky * 64 + kx) * 16384 + b * 128 + c];
    }
    __syncthreads();
    for (int idx = t; idx < 8192; idx += 256) {
        int o = idx >> 7, r = idx & 127, ri = r >> 6, kx = r & 63;
        g_xf[(size_t)(b * 64 + o) * 8192 + ri * 4096 + ky * 64 + kx] =
            s[(ri * 64 + o) * 65 + kx];
    }
}

// ---------------- weight fold: wt[mode][i][o] = spec[i][o][mode] + mlp[o][i] ----------------
__global__ void k_wt(const float* __restrict__ spec, const float* __restrict__ mlp) {
    __shared__ float tile[32][33];
    int x = blockIdx.x * 32 + threadIdx.x;   // mode
    int yb = blockIdx.y * 32;                // io
#pragma unroll
    for (int j = 0; j < 32; j += 8)
        tile[threadIdx.y + j][threadIdx.x] = spec[(size_t)(yb + threadIdx.y + j) * 4096 + x];
    __syncthreads();
    int io2 = yb + threadIdx.x;
    float madd = mlp[(io2 & 63) * 64 + (io2 >> 6)];
    int mb = blockIdx.x * 32;
#pragma unroll
    for (int j = 0; j < 32; j += 8)
        g_wt[(size_t)(mb + threadIdx.y + j) * 4096 + io2] =
            tile[threadIdx.x][threadIdx.y + j] + madd;
}

// ---------------- per-mode GEMM: [256x64] @ [64x64] ----------------
__global__ __launch_bounds__(256) void k_sgemm() {
    extern __shared__ float sm[];
    float* As = sm;                // [256][65]
    float* Ws = sm + 256 * 65;     // [64][68]
    int mode = blockIdx.x, t = threadIdx.x;
    const float* asrc = g_xfm + (size_t)mode * 16384;
    const float* wsrc = g_wt + (size_t)mode * 4096;
    for (int idx = t; idx < 16384; idx += 256) {
        int r = idx >> 6, i = idx & 63;
        As[r * 65 + i] = asrc[idx];
    }
    for (int idx = t; idx < 4096; idx += 256) {
        int i = idx >> 6, o = idx & 63;
        Ws[i * 68 + o] = wsrc[idx];
    }
    __syncthreads();
    int ty = t >> 2, tx = t & 3;   // rows 4, cols 16
    float acc[4][16];
#pragma unroll
    for (int r = 0; r < 4; r++)
#pragma unroll
        for (int c = 0; c < 16; c++) acc[r][c] = 0.f;
#pragma unroll 2
    for (int k = 0; k < 64; k++) {
        float a[4];
#pragma unroll
        for (int r = 0; r < 4; r++) a[r] = As[(ty * 4 + r) * 65 + k];
        float bb[16];
#pragma unroll
        for (int q = 0; q < 4; q++) {
            float4 v = *(const float4*)(Ws + k * 68 + tx * 16 + q * 4);
            bb[q * 4] = v.x; bb[q * 4 + 1] = v.y; bb[q * 4 + 2] = v.z; bb[q * 4 + 3] = v.w;
        }
#pragma unroll
        for (int r = 0; r < 4; r++)
#pragma unroll
            for (int c = 0; c < 16; c++) acc[r][c] = fmaf(a[r], bb[c], acc[r][c]);
    }
    float* dst = g_s1 + (size_t)mode * 16384;
#pragma unroll
    for (int r = 0; r < 4; r++) {
        int row = ty * 4 + r;
#pragma unroll
        for (int q = 0; q < 4; q++)
            *(float4*)(dst + row * 64 + tx * 16 + q * 4) =
                make_float4(acc[r][q * 4], acc[r][q * 4 + 1], acc[r][q * 4 + 2], acc[r][q * 4 + 3]);
    }
}

// ---------------- inverse width + bias + exact GELU ----------------
__global__ __launch_bounds__(256) void k_inv(const float* __restrict__ sb,
                                             const float* __restrict__ mb) {
    extern __shared__ float sm[];
    float* Us = sm;              // [64][129]
    float* Bs = sm + 64 * 129;   // [128][128]
    int bc = blockIdx.x, t = threadIdx.x;
    const float* src = g_s1 + (size_t)bc * 8192;
    for (int idx = t; idx < 8192; idx += 256) {
        int ri = idx >> 12, h = (idx >> 6) & 63, kx = idx & 63;
        Us[h * 129 + ri * 64 + kx] = src[idx];
    }
    for (int idx = t; idx < 16384; idx += 256) Bs[idx] = g_invW[idx];
    __syncthreads();
    int ty = t >> 4, tx = t & 15;
    float acc[4][8];
#pragma unroll
    for (int r = 0; r < 4; r++)
#pragma unroll
        for (int c = 0; c < 8; c++) acc[r][c] = 0.f;
#pragma unroll 2
    for (int k = 0; k < 128; k++) {
        float a[4];
#pragma unroll
        for (int r = 0; r < 4; r++) a[r] = Us[(ty * 4 + r) * 129 + k];
        float4 b0 = *(const float4*)(Bs + k * 128 + tx * 8);
        float4 b1 = *(const float4*)(Bs + k * 128 + tx * 8 + 4);
        float bb[8] = {b0.x, b0.y, b0.z, b0.w, b1.x, b1.y, b1.z, b1.w};
#pragma unroll
        for (int r = 0; r < 4; r++)
#pragma unroll
            for (int c = 0; c < 8; c++) acc[r][c] = fmaf(a[r], bb[c], acc[r][c]);
    }
    int c = bc & 63;
    float bias = __ldg(sb + c) + __ldg(mb + c);
    float* dst = g_x + (size_t)bc * HW_;
#pragma unroll
    for (int r = 0; r < 4; r++) {
        int h = ty * 4 + r;
#pragma unroll
        for (int j = 0; j < 8; j++) {
            int w = tx * 8 + j;
            if (w < 126) {
                float v = acc[r][j] + bias;
                dst[h * 126 + w] = 0.5f * v * (1.0f + erff(v * 0.70710678118654752f));
            }
        }
    }
}

// ---------------- decoder 1x1 conv 64 -> 1 ----------------
__global__ __launch_bounds__(256) void k_dec(const float* __restrict__ dw,
                                             const float* __restrict__ db,
                                             float* __restrict__ out) {
    __shared__ float sw[64];
    int b = blockIdx.x, t = threadIdx.x;
    if (t < 64) sw[t] = dw[t];
    __syncthreads();
    float bias = __ldg(db);
    for (int p = t; p < HW_; p += 256) {
        float s = bias;
        const float* base = g_x + (size_t)b * 64 * HW_ + p;
#pragma unroll 8
        for (int c = 0; c < 64; c++) s = fmaf(sw[c], base[(size_t)c * HW_], s);
        out[(size_t)b * HW_ + p] = s;
    }
}

extern "C" void kernel_launch(void* const* d_in, const int* in_sizes, int n_in,
                              void* d_out, int out_size) {
    const float* x       = (const float*)d_in[0];
    const float* mode_w  = (const float*)d_in[1];
    const float* enc_w   = (const float*)d_in[2];
    const float* enc_b   = (const float*)d_in[3];
    const float* dec_w   = (const float*)d_in[4];
    const float* dec_b   = (const float*)d_in[5];
    const float* spec_w  = (const float*)d_in[6];
    const float* spec_b  = (const float*)d_in[7];
    const float* mlp_w   = (const float*)d_in[8];
    const float* mlp_b   = (const float*)d_in[9];
    float* out = (float*)d_out;

    const int smemF = (64 * 129 + 126 * 128) * 4;   // k_fwdW  ~97.5KB
    const int smemH = (16384 + 8192) * 4;           // k_hdft  96KB
    const int smemG = (256 * 65 + 64 * 68) * 4;     // k_sgemm ~84KB
    const int smemI = (64 * 129 + 16384) * 4;       // k_inv   ~98.5KB
    cudaFuncSetAttribute(k_fwdW,  cudaFuncAttributeMaxDynamicSharedMemorySize, smemF);
    cudaFuncSetAttribute(k_hdft,  cudaFuncAttributeMaxDynamicSharedMemorySize, smemH);
    cudaFuncSetAttribute(k_sgemm, cudaFuncAttributeMaxDynamicSharedMemorySize, smemG);
    cudaFuncSetAttribute(k_inv,   cudaFuncAttributeMaxDynamicSharedMemorySize, smemI);

    k_basis<<<64, 256>>>(mode_w);
    k_enc<<<8192, 256>>>(x, enc_w, enc_b);

    for (int l = 0; l < 4; l++) {
        k_wt<<<dim3(128, 128), dim3(32, 8)>>>(spec_w + (size_t)l * 16777216,
                                              mlp_w + (size_t)l * 4096);
        k_fwdW<<<8192, 256, smemF>>>();
        k_hdft<<<8192, 256, smemH>>>(1);
        k_t1<<<8192, 256>>>();
        k_sgemm<<<4096, 256, smemG>>>();
        k_t2<<<8192, 256>>>();
        k_hdft<<<8192, 256, smemH>>>(0);
        k_inv<<<8192, 256, smemI>>>(spec_b + l * 64, mlp_b + l * 64);
    }
    k_dec<<<128, 256>>>(dec_w, dec_b, out);
}